// round 17
// baseline (speedup 1.0000x reference)
#include <cuda_runtime.h>
#include <cstdint>

// Problem constants
#define NBATCH   64
#define NBINS    256
#define TOTAL_F4 (1u << 23)        // 2 tensors * 64 batches * 65536 float4
#define PAIR_F4  (1u << 16)        // float4 per (tensor,batch) pair
#define NPAIRS   128               // pair = tensor*64 + batch
#define NBLOCKS  296               // ~2 per SM on GB300 (152 SMs), single wave
#define NTHREADS 512

// Scratch (no device allocation allowed). Zero-initialized at module load;
// every consumer resets what it consumed, keeping graph replays correct.
__device__ unsigned int g_dir[NPAIRS][NBINS];  // per-pair histogram
__device__ float        g_kl[NBATCH];
__device__ unsigned int g_bctr[NBATCH];        // per-batch flush tickets
__device__ unsigned int g_ctr;                 // global ticket

// Exact float->small-int for integer-valued f in [0,255]: low byte of
// bits(f + 2^23). FADD+LOP instead of the F2I conversion pipe.
__device__ __forceinline__ unsigned int bin_of(float f) {
    return __float_as_uint(f + 8388608.0f) & 0xFFu;
}

// Number of blocks whose range intersects pair p (floor-division duality
// with the range construction below).
__device__ __forceinline__ unsigned int pair_count(unsigned int p) {
    unsigned long long fb = (((unsigned long long)p << 16) * NBLOCKS) >> 23;
    unsigned long long lb = (((((unsigned long long)(p + 1)) << 16) - 1ull) * NBLOCKS) >> 23;
    return (unsigned int)(lb - fb + 1ull);
}

// ---------------------------------------------------------------------------
// Balanced fused kernel. grid = 296 blocks x 512 threads, 2 blocks/SM.
// Each block owns an equal flat f4 range [b*2^23/296, (b+1)*2^23/296),
// split into <=2 segments at (tensor,batch) boundaries. Per segment:
// bank-exclusive smem histogram (the measured ATOMS wall, ~4.2 lanes/cyc/SM),
// then a 256-atomic flush to g_dir[pair][*] and a per-batch ticket. The
// batch's last flusher computes KL inline; the last batch winner reduces.
// ---------------------------------------------------------------------------
__global__ void __launch_bounds__(NTHREADS, 2) fused_kernel(
    const float4* __restrict__ feat_s, const float4* __restrict__ feat_t,
    float* __restrict__ out) {

    __shared__ unsigned int sh[NBINS][32];   // 32 KB: [bin][lane-column]
    __shared__ float rs[NBINS];
    __shared__ float rt[NBINS];
    __shared__ unsigned int s_t;             // per-batch ticket broadcast
    __shared__ unsigned int s_g;             // global ticket broadcast

    const int lane = threadIdx.x & 31;

    const unsigned int r0 = (unsigned int)((((unsigned long long)blockIdx.x) << 23) / NBLOCKS);
    const unsigned int r1 = (unsigned int)((((unsigned long long)(blockIdx.x + 1)) << 23) / NBLOCKS);

    unsigned int seg = r0;
    while (seg < r1) {
        const unsigned int pair    = seg >> 16;
        const unsigned int batch   = pair & 63u;
        const unsigned int seg_end = min(r1, (pair + 1u) << 16);

        // ---- init smem histogram ----
        #pragma unroll
        for (int i = threadIdx.x; i < NBINS * 32; i += NTHREADS)
            (&sh[0][0])[i] = 0u;
        __syncthreads();

        // ---- histogram this segment ----
        const float4* __restrict__ sp = (pair < 64u) ? feat_s : feat_t;
        // offsets within the tensor's own f4 array:
        const unsigned int s_off = (seg     - (pair << 16)) + (batch << 16);
        const unsigned int e_off = (seg_end - (pair << 16)) + (batch << 16);

        unsigned int j = s_off + threadIdx.x;
        // batch-8 register MLP main loop
        #pragma unroll 1
        while (j + 7u * NTHREADS < e_off) {
            float4 v[8];
            #pragma unroll
            for (int k = 0; k < 8; k++)
                v[k] = __ldcs(&sp[j + (unsigned int)k * NTHREADS]);
            #pragma unroll
            for (int k = 0; k < 8; k++) {
                atomicAdd(&sh[bin_of(v[k].x)][lane], 1u);
                atomicAdd(&sh[bin_of(v[k].y)][lane], 1u);
                atomicAdd(&sh[bin_of(v[k].z)][lane], 1u);
                atomicAdd(&sh[bin_of(v[k].w)][lane], 1u);
            }
            j += 8u * NTHREADS;
        }
        // tail (per-thread guarded)
        #pragma unroll 1
        while (j < e_off) {
            float4 v = __ldcs(&sp[j]);
            atomicAdd(&sh[bin_of(v.x)][lane], 1u);
            atomicAdd(&sh[bin_of(v.y)][lane], 1u);
            atomicAdd(&sh[bin_of(v.z)][lane], 1u);
            atomicAdd(&sh[bin_of(v.w)][lane], 1u);
            j += NTHREADS;
        }
        __syncthreads();

        // ---- flush: reduce lane columns, one global atomic per bin ----
        if (threadIdx.x < NBINS) {
            const int b = threadIdx.x;
            unsigned int sum = 0;
            #pragma unroll
            for (int k = 0; k < 32; k++) sum += sh[b][(k + b) & 31];
            if (sum) atomicAdd(&g_dir[pair][b], sum);
        }
        __syncthreads();

        // ---- per-batch ticket ----
        if (threadIdx.x == 0) {
            __threadfence();
            s_t = atomicAdd(&g_bctr[batch], 1u) + 1u;
        }
        __syncthreads();

        const unsigned int target = pair_count(batch) + pair_count(batch + 64u);
        if (s_t == target) {
            // ===== last flusher for this batch: compute KL(batch) =====
            __threadfence();  // acquire: all flushes of this batch visible

            const int bn = threadIdx.x;   // bin id for threads < NBINS
            float es = 0.f, et = 0.f, as_ = 0.f, at_ = 0.f;
            if (bn < NBINS) {
                unsigned int cs = *((volatile unsigned int*)&g_dir[batch][bn]);
                unsigned int ct = *((volatile unsigned int*)&g_dir[batch + 64u][bn]);
                // reset for next graph replay (we own these words now)
                g_dir[batch][bn] = 0u;
                g_dir[batch + 64u][bn] = 0u;

                as_ = (float)cs + 1e-8f;
                at_ = (float)ct + 1e-8f;
                es = sqrtf(sqrtf(as_));   // (a)^(1/T), T = 4
                et = sqrtf(sqrtf(at_));
                rs[bn] = es; rt[bn] = et;
            }
            __syncthreads();
            #pragma unroll
            for (int s = NBINS / 2; s > 0; s >>= 1) {
                if (bn < s) { rs[bn] += rs[bn + s]; rt[bn] += rt[bn + s]; }
                __syncthreads();
            }
            float Ss = rs[0];
            float St = rt[0];
            __syncthreads();

            if (bn < NBINS) {
                float pt = et / St;                                   // softmax target
                float diff = 0.25f * logf(at_ / as_) - logf(St / Ss); // log p_t - log p_s
                rs[bn] = pt * diff;
            }
            __syncthreads();
            #pragma unroll
            for (int s = NBINS / 2; s > 0; s >>= 1) {
                if (bn < s) rs[bn] += rs[bn + s];
                __syncthreads();
            }

            // publish per-batch KL, reset batch ticket, take global ticket
            if (threadIdx.x == 0) {
                g_kl[batch] = rs[0];
                g_bctr[batch] = 0u;        // ready for next graph replay
                __threadfence();
                s_g = atomicAdd(&g_ctr, 1u);
            }
            __syncthreads();

            if (s_g == NBATCH - 1) {
                // ===== very last batch winner: deterministic final sum =====
                __threadfence();
                if (threadIdx.x < NBATCH)
                    rs[threadIdx.x] = *((volatile float*)&g_kl[threadIdx.x]);
                __syncthreads();
                #pragma unroll
                for (int s = NBATCH / 2; s > 0; s >>= 1) {
                    if (threadIdx.x < s) rs[threadIdx.x] += rs[threadIdx.x + s];
                    __syncthreads();
                }
                if (threadIdx.x == 0) {
                    out[0] = rs[0] * (16.0f / (float)NBATCH);  // * T^2 / N
                    g_ctr = 0u;                                // ready for replay
                }
            }
            __syncthreads();
        }

        seg = seg_end;
    }
}

// ---------------------------------------------------------------------------
extern "C" void kernel_launch(void* const* d_in, const int* in_sizes, int n_in,
                              void* d_out, int out_size) {
    const float4* feat_s = (const float4*)d_in[0];
    const float4* feat_t = (const float4*)d_in[1];
    float* out = (float*)d_out;

    (void)in_sizes; (void)n_in; (void)out_size;

    fused_kernel<<<NBLOCKS, NTHREADS>>>(feat_s, feat_t, out);
}